// round 13
// baseline (speedup 1.0000x reference)
#include <cuda_runtime.h>
#include <stdint.h>

// Problem shape (static)
#define B 32
#define L 4
#define S 512
#define D 768
#define G 24        // NUM_SEGMENTS
#define NCHUNK 18   // 6 dslices * 18 chunks * 32 batches = 3456 CTAs (~2.9 waves @ occ 8)

// Output layout (float32, tuple-order concat):
//   word [B,S,D] | sent [B,D] | seg [B,G,D] | mask [B,G]
#define OFF_SENT ((size_t)B * S * D)
#define OFF_SEG  (OFF_SENT + (size_t)B * D)
#define OFF_MASK (OFF_SEG + (size_t)B * G * D)
// region accumulated with atomics -> must start at zero: sent + seg (contiguous)
#define ZERO_N   ((size_t)B * D + (size_t)B * G * D)

// grid: (6 dslices * NCHUNK, B), block: 128 threads (each owns one d column)
__global__ void __launch_bounds__(128, 8)
bert_agg_kernel(const float* __restrict__ emb,
                const int*   __restrict__ tg,
                const int*   __restrict__ sg,
                float*       __restrict__ out)
{
    const int b      = blockIdx.y;
    const int chunk  = blockIdx.x / 6;
    const int dslice = blockIdx.x % 6;
    const int d      = dslice * 128 + threadIdx.x;

    __shared__ int s_tg[S];
    __shared__ int s_sg[S];
    for (int i = threadIdx.x; i < S; i += 128) {
        s_tg[i] = tg[b * S + i];
        s_sg[i] = sg[b * S + i];
    }
    __syncthreads();

    // ---- chunk bounds, snapped to word-run boundaries (block-uniform) ----
    int ts = (chunk * S) / NCHUNK;
    while (ts > 0 && ts < S && s_tg[ts] == s_tg[ts - 1]) ++ts;
    int te;
    if (chunk == NCHUNK - 1) {
        te = S;
    } else {
        te = ((chunk + 1) * S) / NCHUNK;
        while (te < S && s_tg[te] == s_tg[te - 1]) ++te;
    }

    // 32-bit offsets (max index < 2^26, well within int range)
    const int   LS   = S * D;                 // layer stride in floats
    const float* ep  = emb + (b * L * S * D) + d;
    float*      wout = out + (b * S * D) + d;
    float*      gout = out + OFF_SEG + (b * G * D) + d;

    if (ts < te) {
        // leading word gap (only the chunk starting at token 0)
        if (ts == 0) {
            const int firstw = s_tg[0];
            for (int z = 0; z < firstw; ++z) wout[z * D] = 0.f;
        }

        float sent   = 0.f;
        int   cur_g  = s_tg[ts];
        float wacc   = 0.f;
        int   cur_sg = s_sg[cur_g];
        float gacc   = 0.f;

        // ---- streaming: 4 tokens x 4 layers in flight (16 independent LDG.32) ----
        float v0[4], v1[4], v2[4], v3[4];
#pragma unroll
        for (int i = 0; i < 4; ++i) {
            const int t = (ts + i < S) ? (ts + i) : (S - 1);
            const float* p = ep + t * D;
            v0[i] = p[0];
            v1[i] = p[LS];
            v2[i] = p[2 * LS];
            v3[i] = p[3 * LS];
        }

#pragma unroll 1
        for (int tc = ts; tc < te; tc += 4) {
            float e[4];
#pragma unroll
            for (int i = 0; i < 4; ++i)
                e[i] = (v0[i] + v1[i]) + (v2[i] + v3[i]);

            const int tn = tc + 4;
            if (tn < te) {
#pragma unroll
                for (int i = 0; i < 4; ++i) {
                    const int t = (tn + i < S) ? (tn + i) : (S - 1);
                    const float* p = ep + t * D;
                    v0[i] = p[0];
                    v1[i] = p[LS];
                    v2[i] = p[2 * LS];
                    v3[i] = p[3 * LS];
                }
            }

            const int n = te - tc;
#pragma unroll
            for (int i = 0; i < 4; ++i) {
                if (i < n) {
                    const int g = s_tg[tc + i];
                    if (g != cur_g) {
                        // flush completed word run (owned exclusively by this chunk)
                        wout[cur_g * D] = wacc;
                        const int mysg = s_sg[cur_g];
                        if (mysg != cur_sg) {
                            if (gacc != 0.f) atomicAdd(&gout[cur_sg * D], gacc);
                            gacc   = 0.f;
                            cur_sg = mysg;
                        }
                        gacc += wacc;
                        // zero skipped word slots interior to this chunk's range
                        for (int z = cur_g + 1; z < g; ++z)
                            wout[z * D] = 0.f;
                        wacc  = 0.f;
                        cur_g = g;
                    }
                    wacc += e[i];
                    sent += e[i];
                }
            }
        }

        // ---- final flushes ----
        wout[cur_g * D] = wacc;
        {
            const int mysg = s_sg[cur_g];
            if (mysg != cur_sg) {
                if (gacc != 0.f) atomicAdd(&gout[cur_sg * D], gacc);
                gacc   = 0.f;
                cur_sg = mysg;
            }
            gacc += wacc;
        }
        atomicAdd(&gout[cur_sg * D], gacc);

        // trailing word gap owned by this chunk
        {
            const int nextw = (te < S) ? s_tg[te] : S;
            for (int z = cur_g + 1; z < nextw; ++z)
                wout[z * D] = 0.f;
        }

        // sentence partial: mean over 512 padded word slots == total sum / 512
        atomicAdd(&out[OFF_SENT + b * D + d], sent * (1.0f / 512.0f));
    }

    // seg_mask (sorted segment_ids -> max is last element); one CTA per batch
    if (blockIdx.x == 0 && threadIdx.x < G) {
        const int seg_num = s_sg[S - 1] + 1;
        out[OFF_MASK + (size_t)b * G + threadIdx.x] =
            (threadIdx.x >= seg_num) ? 1.0f : 0.0f;
    }
}

extern "C" void kernel_launch(void* const* d_in, const int* in_sizes, int n_in,
                              void* d_out, int out_size)
{
    const float* emb = (const float*)d_in[0];   // embeddings      [B,L,S,D] f32
    const int*   tg  = (const int*)  d_in[1];   // token_group_ids [B,S] i32
    const int*   sg  = (const int*)  d_in[2];   // segment_ids     [B,S] i32
    float*       out = (float*)d_out;

    // zero the atomically-accumulated region (sent + seg) via a memset node
    cudaMemsetAsync(out + OFF_SENT, 0, ZERO_N * sizeof(float));

    dim3 grid(6 * NCHUNK, B);   // (108, 32) = 3456 CTAs (~2.9 waves @ occ 8)
    bert_agg_kernel<<<grid, 128>>>(emb, tg, sg, out);
}